// round 5
// baseline (speedup 1.0000x reference)
#include <cuda_runtime.h>
#include <cuda_bf16.h>
#include <math.h>

// Problem dims
#define Bv 128
#define Tv 1024
#define Iv 512
#define Hv 1024
#define Ov 256

#define NBLK_SCAN 128   // 16 k-chunks x 8 n-tiles
#define KCHUNKS   16    // K split of the recurrent GEMM (64 each)

typedef unsigned long long ull;

// -------- scratch (device globals: no allocation allowed) --------
__device__ float g_xp[(size_t)Tv * Bv * Hv];        // [t][b][h]  512 MB
__device__ float g_h[2][Bv * Hv];                   // hidden state double buffer
__device__ float g_part[KCHUNKS][Bv * Hv];          // split-K partials (8 MB)
// flag barrier: one 128B-spaced line per CTA; reset to 0 at end of each launch
__device__ unsigned g_flag[NBLK_SCAN * 32];
__device__ unsigned g_gen;                          // monotonic release word

// -------- packed f32x2 helpers (full-rate fp32 on sm_103a) --------
__device__ __forceinline__ void ffma2(ull& d, ull a, ull b) {
    asm("fma.rn.f32x2 %0, %1, %2, %0;" : "+l"(d) : "l"(a), "l"(b));
}
__device__ __forceinline__ ull pack2(float lo, float hi) {
    ull r; asm("mov.b64 %0, {%1, %2};" : "=l"(r) : "f"(lo), "f"(hi)); return r;
}
__device__ __forceinline__ float2 unpack2(ull v) {
    float2 r; asm("mov.b64 {%0, %1}, %2;" : "=f"(r.x), "=f"(r.y) : "l"(v)); return r;
}

// -------- flag-barrier primitives --------
__device__ __forceinline__ void flag_arrive(int bi, unsigned n) {
    // cumulative fence: CTA's prior stores (ordered to thread0 by __syncthreads)
    // become gpu-visible before the flag store is observed
    asm volatile("fence.acq_rel.gpu;" ::: "memory");
    asm volatile("st.relaxed.gpu.u32 [%0], %1;"
                 :: "l"(&g_flag[bi * 32]), "r"(n) : "memory");
}
// CTA 0 only: all 256 threads call; tids 0..127 each poll one flag
__device__ __forceinline__ void master_collect(int tid, unsigned n, unsigned gen0) {
    if (tid < NBLK_SCAN) {
        const unsigned* f = &g_flag[tid * 32];
        unsigned v;
        do {
            asm volatile("ld.relaxed.gpu.u32 %0, [%1];" : "=r"(v) : "l"(f) : "memory");
        } while (v < n);
        asm volatile("fence.acq_rel.gpu;" ::: "memory");
    }
    __syncthreads();
    if (tid == 0) {
        asm volatile("fence.acq_rel.gpu;" ::: "memory");
        asm volatile("st.relaxed.gpu.u32 [%0], %1;"
                     :: "l"(&g_gen), "r"(gen0 + n) : "memory");
    }
}
__device__ __forceinline__ void gen_spin(unsigned gen0, unsigned n) {
    unsigned cur;
    do {
        asm volatile("ld.relaxed.gpu.u32 %0, [%1];" : "=r"(cur) : "l"(&g_gen) : "memory");
    } while ((cur - gen0) < n);
    asm volatile("fence.acq_rel.gpu;" ::: "memory");
}

// ============================================================
// Kernel A: xp[t][b][h] = x[b][t][:] @ kernel[:, h] + bias[h]
// 128x128 block tile, 8x8 thread tile, FFMA2 (register-side A duplication)
// ============================================================
__global__ void __launch_bounds__(256, 2) xp_gemm(
    const float* __restrict__ X, const float* __restrict__ WK,
    const float* __restrict__ bias)
{
    __shared__ float As[8][128];
    __shared__ float Bs[8][128];

    const int tid = threadIdx.x;
    const int tx = tid & 15;       // N direction (0..15)
    const int ty = tid >> 4;       // M direction (0..15)
    const int n0 = blockIdx.x * 128;
    const int m0 = blockIdx.y * 128;

    const int arow = tid >> 1;            // 0..127
    const int acol = (tid & 1) * 4;       // 0 or 4
    const int brow = tid >> 5;            // 0..7
    const int bcol = (tid & 31) * 4;      // 0..124

    ull acc[8][4];
#pragma unroll
    for (int i = 0; i < 8; i++)
#pragma unroll
        for (int j = 0; j < 4; j++) acc[i][j] = 0ull;

    const float* Aptr = X + (size_t)(m0 + arow) * Iv + acol;
    const float* Bptr = WK + (size_t)brow * Hv + n0 + bcol;

    for (int k0 = 0; k0 < Iv; k0 += 8) {
        float4 av = *(const float4*)(Aptr + k0);
        float4 bv = *(const float4*)(Bptr + (size_t)k0 * Hv);
        __syncthreads();
        As[acol + 0][arow] = av.x;
        As[acol + 1][arow] = av.y;
        As[acol + 2][arow] = av.z;
        As[acol + 3][arow] = av.w;
        *(float4*)&Bs[brow][bcol] = bv;
        __syncthreads();
#pragma unroll
        for (int kk = 0; kk < 8; kk++) {
            float4 a0 = *(const float4*)&As[kk][ty * 8];
            float4 a1 = *(const float4*)&As[kk][ty * 8 + 4];
            ull b0 = *(const ull*)&Bs[kk][tx * 8 + 0];
            ull b1 = *(const ull*)&Bs[kk][tx * 8 + 2];
            ull b2 = *(const ull*)&Bs[kk][tx * 8 + 4];
            ull b3 = *(const ull*)&Bs[kk][tx * 8 + 6];
            float af[8] = {a0.x, a0.y, a0.z, a0.w, a1.x, a1.y, a1.z, a1.w};
#pragma unroll
            for (int i = 0; i < 8; i++) {
                ull ap = pack2(af[i], af[i]);
                ffma2(acc[i][0], ap, b0);
                ffma2(acc[i][1], ap, b1);
                ffma2(acc[i][2], ap, b2);
                ffma2(acc[i][3], ap, b3);
            }
        }
    }

    float4 bb0 = *(const float4*)&bias[n0 + tx * 8];
    float4 bb1 = *(const float4*)&bias[n0 + tx * 8 + 4];

#pragma unroll
    for (int i = 0; i < 8; i++) {
        int m = m0 + ty * 8 + i;
        int bb = m >> 10;       // / T
        int tt = m & 1023;      // % T
        float* dst = g_xp + ((size_t)tt * Bv + bb) * Hv + n0 + tx * 8;
        float2 p0 = unpack2(acc[i][0]);
        float2 p1 = unpack2(acc[i][1]);
        float2 p2 = unpack2(acc[i][2]);
        float2 p3 = unpack2(acc[i][3]);
        float4 v0 = {p0.x + bb0.x, p0.y + bb0.y, p1.x + bb0.z, p1.y + bb0.w};
        float4 v1 = {p2.x + bb1.x, p2.y + bb1.y, p3.x + bb1.z, p3.y + bb1.w};
        *(float4*)(dst + 0) = v0;
        *(float4*)(dst + 4) = v1;
    }
}

// ============================================================
// Kernel B: persistent recurrent scan, Wr resident in SMEM.
// block = (kc, nt): part[kc][:, ntile] = h[:, kcslice] @ Wr[kcslice, ntile]
// SMEM: Ws[64][128] floats (32KB, loaded once) + As[64][128] floats (32KB)
// Flag barrier: arrivals are plain stores; CTA0 collects + releases g_gen.
// ============================================================
__global__ void __launch_bounds__(256, 1) scan_kernel(const float* __restrict__ WR)
{
    extern __shared__ float smem_dyn[];
    float* Ws = smem_dyn;            // [64][128] = 8192 floats, 32KB
    float* As = smem_dyn + 8192;     // [64][128] = 8192 floats, 32KB

    const int tid = threadIdx.x;
    const int tx = tid & 15;
    const int ty = tid >> 4;
    const int bi = blockIdx.x;
    const int kc = bi >> 3;               // 0..15
    const int nt = bi & 7;                // 0..7
    const int kbase = kc * 64;
    const int nbase = nt * 128;
    const bool master = (bi == 0);

    const int arow = tid >> 1;            // 0..127
    const int acol = (tid & 1) * 4;       // 0 or 4
    const int brow = tid >> 5;            // 0..7
    const int bcol = (tid & 31) * 4;      // 0..124

    const int e = (bi * 256 + tid) * 4;   // flat element [0, 131072)

    // gen baseline (read before our first arrival; gen can't advance until
    // all CTAs arrive at instance 1, so this is race-free)
    unsigned gen0 = 0;
    if (tid == 0) {
        asm volatile("ld.relaxed.gpu.u32 %0, [%1];" : "=r"(gen0) : "l"(&g_gen));
    }

    // ---- load resident Wr slice: Ws[k][n] = WR[kbase+k][nbase+n] ----
#pragma unroll
    for (int c = 0; c < 8; c++) {
        int k = c * 8 + brow;
        float4 v = *(const float4*)(WR + (size_t)(kbase + k) * Hv + nbase + bcol);
        *(float4*)&Ws[k * 128 + bcol] = v;
    }

    // zero initial hidden state
    {
        float4 z = {0.f, 0.f, 0.f, 0.f};
        *(float4*)&g_h[0][e] = z;
    }

    // prefetch xp[0]
    float4 xpv = *(const float4*)&g_xp[e];

    // ---- initial barrier (instance 1) ----
    __syncthreads();
    if (tid == 0) flag_arrive(bi, 1u);
    if (master) master_collect(tid, 1u, gen0);
    if (tid == 0) gen_spin(gen0, 1u);
    __syncthreads();

    int cur = 0;
#pragma unroll 1
    for (int t = 0; t < Tv; t++) {
        const float* hcur = g_h[cur];
        const unsigned n1 = 2u + 2u * t;   // barrier instances
        const unsigned n2 = 3u + 2u * t;

        // ---- stage h slice (transposed floats): As[k][row] ----
#pragma unroll
        for (int c = 0; c < 8; c++) {
            int k = c * 8 + acol;
            float4 av = __ldcg((const float4*)(hcur + (size_t)arow * Hv + kbase + c * 8 + acol));
            As[(k + 0) * 128 + arow] = av.x;
            As[(k + 1) * 128 + arow] = av.y;
            As[(k + 2) * 128 + arow] = av.z;
            As[(k + 3) * 128 + arow] = av.w;
        }
        __syncthreads();

        // ---- phase 1: partial GEMM 128x128x64 from SMEM ----
        ull acc[8][4];
#pragma unroll
        for (int i = 0; i < 8; i++)
#pragma unroll
            for (int j = 0; j < 4; j++) acc[i][j] = 0ull;

#pragma unroll 8
        for (int kk = 0; kk < 64; kk++) {
            float4 a0 = *(const float4*)&As[kk * 128 + ty * 8];
            float4 a1 = *(const float4*)&As[kk * 128 + ty * 8 + 4];
            ull b0 = *(const ull*)&Ws[kk * 128 + tx * 8 + 0];
            ull b1 = *(const ull*)&Ws[kk * 128 + tx * 8 + 2];
            ull b2 = *(const ull*)&Ws[kk * 128 + tx * 8 + 4];
            ull b3 = *(const ull*)&Ws[kk * 128 + tx * 8 + 6];
            float af[8] = {a0.x, a0.y, a0.z, a0.w, a1.x, a1.y, a1.z, a1.w};
#pragma unroll
            for (int i = 0; i < 8; i++) {
                ull ap = pack2(af[i], af[i]);
                ffma2(acc[i][0], ap, b0);
                ffma2(acc[i][1], ap, b1);
                ffma2(acc[i][2], ap, b2);
                ffma2(acc[i][3], ap, b3);
            }
        }

        // ---- write split-K partials ----
        {
            float* P = g_part[kc];
#pragma unroll
            for (int i = 0; i < 8; i++) {
                int row = ty * 8 + i;
                float2 p0 = unpack2(acc[i][0]);
                float2 p1 = unpack2(acc[i][1]);
                float2 p2 = unpack2(acc[i][2]);
                float2 p3 = unpack2(acc[i][3]);
                float4 v0 = {p0.x, p0.y, p1.x, p1.y};
                float4 v1 = {p2.x, p2.y, p3.x, p3.y};
                float* dst = P + (size_t)row * Hv + nbase + tx * 8;
                *(float4*)(dst + 0) = v0;
                *(float4*)(dst + 4) = v1;
            }
        }

        // ---- barrier 1 ----
        __syncthreads();
        if (tid == 0) flag_arrive(bi, n1);
        if (master) master_collect(tid, n1, gen0);
        if (tid == 0) gen_spin(gen0, n1);
        __syncthreads();

        // ---- phase 2: reduce partials + xp + tanh -> h_next ----
        {
            float4 s = xpv;
#pragma unroll
            for (int c = 0; c < KCHUNKS; c++) {
                float4 p = __ldcg((const float4*)&g_part[c][e]);
                s.x += p.x; s.y += p.y; s.z += p.z; s.w += p.w;
            }
            float4 hn;
            hn.x = tanhf(s.x); hn.y = tanhf(s.y);
            hn.z = tanhf(s.z); hn.w = tanhf(s.w);
            *(float4*)&g_h[cur ^ 1][e] = hn;
        }

        // ---- barrier 2 (prefetch xp[t+1] in the arrive/wait gap) ----
        __syncthreads();
        if (tid == 0) flag_arrive(bi, n2);
        {
            int tn = (t + 1 < Tv) ? (t + 1) : 0;
            xpv = *(const float4*)&g_xp[(size_t)tn * (Bv * Hv) + e];
        }
        if (master) master_collect(tid, n2, gen0);
        if (tid == 0) gen_spin(gen0, n2);
        __syncthreads();

        cur ^= 1;
    }

    // reset own flag for the next launch/replay (sole writer; master has no
    // outstanding polls after the final release)
    if (tid == 0) {
        asm volatile("st.relaxed.gpu.u32 [%0], 0;" :: "l"(&g_flag[bi * 32]) : "memory");
    }
    // T even -> final hidden state ends in g_h[0]
}

// ============================================================
// Kernel C: out[b][o] = h_last[b][:] @ fc_w[:, o] + fc_b[o]
// ============================================================
__global__ void __launch_bounds__(256, 1) fc_kernel(
    const float* __restrict__ fcw, const float* __restrict__ fcb,
    float* __restrict__ out)
{
    __shared__ float hs[Hv];
    const int b = blockIdx.x;
    const float* hrow = g_h[0] + (size_t)b * Hv;
    for (int i = threadIdx.x; i < Hv; i += 256) hs[i] = hrow[i];
    __syncthreads();

    const int o = threadIdx.x;   // 0..255 == Ov
    float acc = 0.f;
#pragma unroll 4
    for (int k = 0; k < Hv; k++) {
        acc = fmaf(hs[k], fcw[(size_t)k * Ov + o], acc);
    }
    out[(size_t)b * Ov + o] = acc + fcb[o];
}

// ============================================================
extern "C" void kernel_launch(void* const* d_in, const int* in_sizes, int n_in,
                              void* d_out, int out_size)
{
    const float* x   = (const float*)d_in[0];   // [B,T,I]
    const float* wk  = (const float*)d_in[1];   // [I,H]
    const float* wr  = (const float*)d_in[2];   // [H,H]
    const float* bs  = (const float*)d_in[3];   // [H]
    const float* fcw = (const float*)d_in[4];   // [H,O]
    const float* fcb = (const float*)d_in[5];   // [O]
    float* out = (float*)d_out;                 // [B,O]

    static int smem_set = 0;
    if (!smem_set) {
        cudaFuncSetAttribute(scan_kernel,
                             cudaFuncAttributeMaxDynamicSharedMemorySize, 65536);
        smem_set = 1;
    }

    dim3 gA(Hv / 128, (Bv * Tv) / 128);         // (8, 1024)
    xp_gemm<<<gA, 256>>>(x, wk, bs);
    scan_kernel<<<NBLK_SCAN, 256, 65536>>>(wr);
    fc_kernel<<<Bv, 256>>>(fcw, fcb, out);
}

// round 7
// speedup vs baseline: 1.5742x; 1.5742x over previous
#include <cuda_runtime.h>
#include <cuda_bf16.h>
#include <math.h>
#include <cstdint>

// Problem dims
#define Bv 128
#define Tv 1024
#define Iv 512
#define Hv 1024
#define Ov 256

#define NBLK_SCAN 128   // 16 k-chunks x 8 n-tiles
#define KCHUNKS   16    // K split of the recurrent GEMM (64 each)

typedef unsigned long long ull;

// -------- scratch (device globals: no allocation allowed) --------
__device__ float g_xp[(size_t)Tv * Bv * Hv];        // [t][b][h]  512 MB
__device__ __nv_bfloat16 g_hh[Bv * Hv];             // hidden state, bf16 hi
__device__ __nv_bfloat16 g_hl[Bv * Hv];             // hidden state, bf16 lo
__device__ float g_part[KCHUNKS][Bv * Hv];          // split-K partials (8 MB)
__device__ unsigned g_bar_count;                    // zero-initialized
__device__ volatile unsigned g_bar_gen;             // generation counter

// -------- packed f32x2 helpers (full-rate fp32 on sm_103a) --------
__device__ __forceinline__ void ffma2(ull& d, ull a, ull b) {
    asm("fma.rn.f32x2 %0, %1, %2, %0;" : "+l"(d) : "l"(a), "l"(b));
}
__device__ __forceinline__ ull pack2(float lo, float hi) {
    ull r; asm("mov.b64 %0, {%1, %2};" : "=l"(r) : "f"(lo), "f"(hi)); return r;
}
__device__ __forceinline__ float2 unpack2(ull v) {
    float2 r; asm("mov.b64 {%0, %1}, %2;" : "=f"(r.x), "=f"(r.y) : "l"(v)); return r;
}

// -------- R2 flat-atomic grid barrier (best measured of 3 designs) --------
__device__ __forceinline__ void grid_bar() {
    __threadfence();
    __syncthreads();
    if (threadIdx.x == 0) {
        unsigned gen = g_bar_gen;
        unsigned prev = atomicAdd(&g_bar_count, 1u);
        if (prev == NBLK_SCAN - 1) {
            g_bar_count = 0;
            __threadfence();
            g_bar_gen = gen + 1;
        } else {
            while (g_bar_gen == gen) { __nanosleep(64); }
        }
    }
    __syncthreads();
}

// -------- mma.sync / ldmatrix helpers (compute_103-baseline features) --------
__device__ __forceinline__ uint32_t smem_u32(const void* p) {
    uint32_t a;
    asm("{ .reg .u64 t; cvta.to.shared.u64 t, %1; cvt.u32.u64 %0, t; }"
        : "=r"(a) : "l"(p));
    return a;
}
__device__ __forceinline__ void ldsm4(uint32_t r[4], uint32_t addr) {
    asm volatile("ldmatrix.sync.aligned.m8n8.x4.shared.b16 {%0,%1,%2,%3}, [%4];"
                 : "=r"(r[0]), "=r"(r[1]), "=r"(r[2]), "=r"(r[3]) : "r"(addr));
}
__device__ __forceinline__ void mma_bf16(float d[4], const uint32_t a[4],
                                         const uint32_t b0, const uint32_t b1) {
    asm volatile(
        "mma.sync.aligned.m16n8k16.row.col.f32.bf16.bf16.f32 "
        "{%0,%1,%2,%3}, {%4,%5,%6,%7}, {%8,%9}, {%0,%1,%2,%3};"
        : "+f"(d[0]), "+f"(d[1]), "+f"(d[2]), "+f"(d[3])
        : "r"(a[0]), "r"(a[1]), "r"(a[2]), "r"(a[3]), "r"(b0), "r"(b1));
}

// ============================================================
// Kernel A: xp[t][b][h] = x[b][t][:] @ kernel[:, h] + bias[h]  (R2, proven)
// ============================================================
__global__ void __launch_bounds__(256, 2) xp_gemm(
    const float* __restrict__ X, const float* __restrict__ WK,
    const float* __restrict__ bias)
{
    __shared__ float As[8][128];
    __shared__ float Bs[8][128];

    const int tid = threadIdx.x;
    const int tx = tid & 15;
    const int ty = tid >> 4;
    const int n0 = blockIdx.x * 128;
    const int m0 = blockIdx.y * 128;

    const int arow = tid >> 1;
    const int acol = (tid & 1) * 4;
    const int brow = tid >> 5;
    const int bcol = (tid & 31) * 4;

    ull acc[8][4];
#pragma unroll
    for (int i = 0; i < 8; i++)
#pragma unroll
        for (int j = 0; j < 4; j++) acc[i][j] = 0ull;

    const float* Aptr = X + (size_t)(m0 + arow) * Iv + acol;
    const float* Bptr = WK + (size_t)brow * Hv + n0 + bcol;

    for (int k0 = 0; k0 < Iv; k0 += 8) {
        float4 av = *(const float4*)(Aptr + k0);
        float4 bv = *(const float4*)(Bptr + (size_t)k0 * Hv);
        __syncthreads();
        As[acol + 0][arow] = av.x;
        As[acol + 1][arow] = av.y;
        As[acol + 2][arow] = av.z;
        As[acol + 3][arow] = av.w;
        *(float4*)&Bs[brow][bcol] = bv;
        __syncthreads();
#pragma unroll
        for (int kk = 0; kk < 8; kk++) {
            float4 a0 = *(const float4*)&As[kk][ty * 8];
            float4 a1 = *(const float4*)&As[kk][ty * 8 + 4];
            ull b0 = *(const ull*)&Bs[kk][tx * 8 + 0];
            ull b1 = *(const ull*)&Bs[kk][tx * 8 + 2];
            ull b2 = *(const ull*)&Bs[kk][tx * 8 + 4];
            ull b3 = *(const ull*)&Bs[kk][tx * 8 + 6];
            float af[8] = {a0.x, a0.y, a0.z, a0.w, a1.x, a1.y, a1.z, a1.w};
#pragma unroll
            for (int i = 0; i < 8; i++) {
                ull ap = pack2(af[i], af[i]);
                ffma2(acc[i][0], ap, b0);
                ffma2(acc[i][1], ap, b1);
                ffma2(acc[i][2], ap, b2);
                ffma2(acc[i][3], ap, b3);
            }
        }
    }

    float4 bb0 = *(const float4*)&bias[n0 + tx * 8];
    float4 bb1 = *(const float4*)&bias[n0 + tx * 8 + 4];

#pragma unroll
    for (int i = 0; i < 8; i++) {
        int m = m0 + ty * 8 + i;
        int bb = m >> 10;
        int tt = m & 1023;
        float* dst = g_xp + ((size_t)tt * Bv + bb) * Hv + n0 + tx * 8;
        float2 p0 = unpack2(acc[i][0]);
        float2 p1 = unpack2(acc[i][1]);
        float2 p2 = unpack2(acc[i][2]);
        float2 p3 = unpack2(acc[i][3]);
        float4 v0 = {p0.x + bb0.x, p0.y + bb0.y, p1.x + bb0.z, p1.y + bb0.w};
        float4 v1 = {p2.x + bb1.x, p2.y + bb1.y, p3.x + bb1.z, p3.y + bb1.w};
        *(float4*)(dst + 0) = v0;
        *(float4*)(dst + 4) = v1;
    }
}

// ============================================================
// Kernel B: persistent scan, mma.sync bf16 3-term split GEMM.
// CTA (kc,nt): D(128x128 f32 regs) = hh*Wh + hl*Wh + hh*Wl over K=64 slice
// SMEM (64KB dyn): Ahh[128][64]bf16 | Ahl | Wh[n:128][k:64]bf16 | Wl
// All tiles 128 rows x 128 bytes, XOR-swizzled (byte^=(row&7)<<4).
// ============================================================
__global__ void __launch_bounds__(256, 1) scan_kernel(const float* __restrict__ WR)
{
    extern __shared__ __align__(1024) char smem[];
    char* sAhh = smem;
    char* sAhl = smem + 16384;
    char* sBwh = smem + 32768;
    char* sBwl = smem + 49152;
    const uint32_t pAhh = smem_u32(smem);
    const uint32_t pAhl = pAhh + 16384;
    const uint32_t pBwh = pAhh + 32768;
    const uint32_t pBwl = pAhh + 49152;

    const int tid = threadIdx.x;
    const int wid = tid >> 5;
    const int lid = tid & 31;
    const int bi = blockIdx.x;
    const int kc = bi >> 3;            // 0..15
    const int nt = bi & 7;             // 0..7
    const int kbase = kc * 64;
    const int nbase = nt * 128;
    const int e = (bi * 256 + tid) * 4;

    // warp tile: 2(M) x 4(N) warps; warp tile 64x32
    const int wm = wid & 1;            // m0 = wm*64
    const int wn = wid >> 1;           // n0 = wn*32

    // ldmatrix lane invariants
    const int rowA = ((lid >> 3) & 1) * 8 + (lid & 7);
    const int khA  = (lid >> 4) * 16;
    const int rowB = ((lid >> 4) & 1) * 8 + (lid & 7);
    const int khB  = ((lid >> 3) & 1) * 16;
    const int sw   = (lid & 7) << 4;
    const uint32_t aHiBase = pAhh + (wm * 64 + rowA) * 128;
    const uint32_t aLoBase = pAhl + (wm * 64 + rowA) * 128;
    const uint32_t bHiBase = pBwh + (wn * 32 + rowB) * 128;
    const uint32_t bLoBase = pBwl + (wn * 32 + rowB) * 128;

    // ---- preload Wr slice, split bf16 hi/lo, layout [n][k], swizzled ----
    for (int idx = tid; idx < 128 * 64; idx += 256) {
        int n = idx & 127;
        int k = idx >> 7;
        float w = WR[(size_t)(kbase + k) * Hv + nbase + n];
        __nv_bfloat16 wh = __float2bfloat16(w);
        __nv_bfloat16 wl = __float2bfloat16(w - __bfloat162float(wh));
        uint32_t off = n * 128 + ((k * 2) ^ ((n & 7) << 4));
        *(__nv_bfloat16*)(sBwh + off) = wh;
        *(__nv_bfloat16*)(sBwl + off) = wl;
    }

    // zero initial hidden state (hi + lo)
    *(ull*)&g_hh[e] = 0ull;
    *(ull*)&g_hl[e] = 0ull;

    // prefetch xp[0]
    float4 xpv = *(const float4*)&g_xp[e];

    grid_bar();

    const int srow = tid >> 1;         // staging row 0..127
    const int soff = (tid & 1) * 64;   // byte half of the 128B row

#pragma unroll 1
    for (int t = 0; t < Tv; t++) {
        // ---- stage h slice (bf16 hi/lo, K-major, swizzled) ----
        {
            const char* sh = (const char*)(g_hh + (size_t)srow * Hv + kbase) + soff;
            const char* sl = (const char*)(g_hl + (size_t)srow * Hv + kbase) + soff;
            uint4 h0 = __ldcg((const uint4*)sh + 0);
            uint4 h1 = __ldcg((const uint4*)sh + 1);
            uint4 h2 = __ldcg((const uint4*)sh + 2);
            uint4 h3 = __ldcg((const uint4*)sh + 3);
            uint4 l0 = __ldcg((const uint4*)sl + 0);
            uint4 l1 = __ldcg((const uint4*)sl + 1);
            uint4 l2 = __ldcg((const uint4*)sl + 2);
            uint4 l3 = __ldcg((const uint4*)sl + 3);
            uint32_t rb = srow * 128;
            uint32_t sws = (srow & 7) << 4;
            *(uint4*)(sAhh + rb + ((soff +  0) ^ sws)) = h0;
            *(uint4*)(sAhh + rb + ((soff + 16) ^ sws)) = h1;
            *(uint4*)(sAhh + rb + ((soff + 32) ^ sws)) = h2;
            *(uint4*)(sAhh + rb + ((soff + 48) ^ sws)) = h3;
            *(uint4*)(sAhl + rb + ((soff +  0) ^ sws)) = l0;
            *(uint4*)(sAhl + rb + ((soff + 16) ^ sws)) = l1;
            *(uint4*)(sAhl + rb + ((soff + 32) ^ sws)) = l2;
            *(uint4*)(sAhl + rb + ((soff + 48) ^ sws)) = l3;
        }
        __syncthreads();

        // ---- mma.sync GEMM: 128x128x64, 3 chains ----
        float D[4][4][4];
#pragma unroll
        for (int i = 0; i < 4; i++)
#pragma unroll
            for (int j = 0; j < 4; j++)
#pragma unroll
                for (int q = 0; q < 4; q++) D[i][j][q] = 0.f;

#pragma unroll
        for (int ks = 0; ks < 4; ks++) {
            const uint32_t koffA = ((ks * 32) | khA) ^ sw;
            const uint32_t koffB = ((ks * 32) | khB) ^ sw;
            uint32_t Ah[4][4], Al[4][4], Bh[2][4], Bl[2][4];
#pragma unroll
            for (int mt = 0; mt < 4; mt++) {
                ldsm4(Ah[mt], aHiBase + mt * 2048 + koffA);
                ldsm4(Al[mt], aLoBase + mt * 2048 + koffA);
            }
#pragma unroll
            for (int np = 0; np < 2; np++) {
                ldsm4(Bh[np], bHiBase + np * 2048 + koffB);
                ldsm4(Bl[np], bLoBase + np * 2048 + koffB);
            }
#pragma unroll
            for (int mt = 0; mt < 4; mt++) {
#pragma unroll
                for (int ntl = 0; ntl < 4; ntl++) {
                    const int np = ntl >> 1, q = (ntl & 1) * 2;
                    mma_bf16(D[mt][ntl], Ah[mt], Bh[np][q], Bh[np][q + 1]);
                    mma_bf16(D[mt][ntl], Al[mt], Bh[np][q], Bh[np][q + 1]);
                    mma_bf16(D[mt][ntl], Ah[mt], Bl[np][q], Bl[np][q + 1]);
                }
            }
        }

        // ---- write split-K partials (c-frag: row g/g+8, col pair) ----
        {
            const int g = lid >> 2, c2 = (lid & 3) * 2;
            float* P = g_part[kc];
#pragma unroll
            for (int mt = 0; mt < 4; mt++) {
#pragma unroll
                for (int ntl = 0; ntl < 4; ntl++) {
                    int row0 = wm * 64 + mt * 16 + g;
                    int col = nbase + wn * 32 + ntl * 8 + c2;
                    float2 v0 = {D[mt][ntl][0], D[mt][ntl][1]};
                    float2 v1 = {D[mt][ntl][2], D[mt][ntl][3]};
                    *(float2*)&P[(size_t)row0 * Hv + col] = v0;
                    *(float2*)&P[(size_t)(row0 + 8) * Hv + col] = v1;
                }
            }
        }

        grid_bar();

        // ---- phase 2: reduce partials + xp + tanh -> h (bf16 hi/lo) ----
        {
            float4 s = xpv;
#pragma unroll
            for (int c = 0; c < KCHUNKS; c++) {
                float4 p = __ldcg((const float4*)&g_part[c][e]);
                s.x += p.x; s.y += p.y; s.z += p.z; s.w += p.w;
            }
            float h[4] = {tanhf(s.x), tanhf(s.y), tanhf(s.z), tanhf(s.w)};
            unsigned short hh[4], hl[4];
#pragma unroll
            for (int j = 0; j < 4; j++) {
                __nv_bfloat16 a = __float2bfloat16(h[j]);
                __nv_bfloat16 b = __float2bfloat16(h[j] - __bfloat162float(a));
                hh[j] = __bfloat16_as_ushort(a);
                hl[j] = __bfloat16_as_ushort(b);
            }
            *(ull*)&g_hh[e] = *(const ull*)hh;
            *(ull*)&g_hl[e] = *(const ull*)hl;
        }

        // prefetch xp[t+1]
        {
            int tn = (t + 1 < Tv) ? (t + 1) : 0;
            xpv = *(const float4*)&g_xp[(size_t)tn * (Bv * Hv) + e];
        }

        grid_bar();
    }
}

// ============================================================
// Kernel C: out[b][o] = h_last[b][:] @ fc_w[:, o] + fc_b[o]
// h reconstructed from bf16 hi+lo (exact to ~2^-17)
// ============================================================
__global__ void __launch_bounds__(256, 1) fc_kernel(
    const float* __restrict__ fcw, const float* __restrict__ fcb,
    float* __restrict__ out)
{
    __shared__ float hs[Hv];
    const int b = blockIdx.x;
    for (int i = threadIdx.x; i < Hv; i += 256) {
        hs[i] = __bfloat162float(g_hh[(size_t)b * Hv + i]) +
                __bfloat162float(g_hl[(size_t)b * Hv + i]);
    }
    __syncthreads();

    const int o = threadIdx.x;
    float acc = 0.f;
#pragma unroll 4
    for (int k = 0; k < Hv; k++) {
        acc = fmaf(hs[k], fcw[(size_t)k * Ov + o], acc);
    }
    out[(size_t)b * Ov + o] = acc + fcb[o];
}

// ============================================================
extern "C" void kernel_launch(void* const* d_in, const int* in_sizes, int n_in,
                              void* d_out, int out_size)
{
    const float* x   = (const float*)d_in[0];
    const float* wk  = (const float*)d_in[1];
    const float* wr  = (const float*)d_in[2];
    const float* bs  = (const float*)d_in[3];
    const float* fcw = (const float*)d_in[4];
    const float* fcb = (const float*)d_in[5];
    float* out = (float*)d_out;

    static int smem_set = 0;
    if (!smem_set) {
        cudaFuncSetAttribute(scan_kernel,
                             cudaFuncAttributeMaxDynamicSharedMemorySize, 65536);
        smem_set = 1;
    }

    dim3 gA(Hv / 128, (Bv * Tv) / 128);
    xp_gemm<<<gA, 256>>>(x, wk, bs);
    scan_kernel<<<NBLK_SCAN, 256, 65536>>>(wr);
    fc_kernel<<<Bv, 256>>>(fcw, fcb, out);
}

// round 8
// speedup vs baseline: 1.7140x; 1.0889x over previous
#include <cuda_runtime.h>
#include <cuda_bf16.h>
#include <math.h>
#include <cstdint>

// Problem dims
#define Bv 128
#define Tv 1024
#define Iv 512
#define Hv 1024
#define Ov 256

#define NBLK_SCAN 128   // 16 k-chunks x 8 n-tiles
#define KCHUNKS   16    // K split of the recurrent GEMM (64 each)

typedef unsigned long long ull;

// -------- scratch (device globals: no allocation allowed) --------
__device__ float g_xp[(size_t)Tv * Bv * Hv];        // [t][b][h]  512 MB
__device__ __nv_bfloat16 g_hh[Bv * Hv];             // hidden state, bf16 hi
__device__ __nv_bfloat16 g_hl[Bv * Hv];             // hidden state, bf16 lo
__device__ float g_part[KCHUNKS][Bv * Hv];          // split-K partials (8 MB)
__device__ __nv_bfloat16 g_wh[Hv * Iv];             // kernel split hi, [n][k]
__device__ __nv_bfloat16 g_wl[Hv * Iv];             // kernel split lo, [n][k]
__device__ unsigned g_bar_count;                    // zero-initialized
__device__ volatile unsigned g_bar_gen;             // generation counter

// -------- R2 flat-atomic grid barrier (best measured of 3 designs) --------
__device__ __forceinline__ void grid_bar() {
    __threadfence();
    __syncthreads();
    if (threadIdx.x == 0) {
        unsigned gen = g_bar_gen;
        unsigned prev = atomicAdd(&g_bar_count, 1u);
        if (prev == NBLK_SCAN - 1) {
            g_bar_count = 0;
            __threadfence();
            g_bar_gen = gen + 1;
        } else {
            while (g_bar_gen == gen) { __nanosleep(64); }
        }
    }
    __syncthreads();
}

// -------- mma.sync / ldmatrix helpers (compute_103-baseline features) --------
__device__ __forceinline__ uint32_t smem_u32(const void* p) {
    uint32_t a;
    asm("{ .reg .u64 t; cvta.to.shared.u64 t, %1; cvt.u32.u64 %0, t; }"
        : "=r"(a) : "l"(p));
    return a;
}
__device__ __forceinline__ void ldsm4(uint32_t r[4], uint32_t addr) {
    asm volatile("ldmatrix.sync.aligned.m8n8.x4.shared.b16 {%0,%1,%2,%3}, [%4];"
                 : "=r"(r[0]), "=r"(r[1]), "=r"(r[2]), "=r"(r[3]) : "r"(addr));
}
__device__ __forceinline__ void mma_bf16(float d[4], const uint32_t a[4],
                                         const uint32_t b0, const uint32_t b1) {
    asm volatile(
        "mma.sync.aligned.m16n8k16.row.col.f32.bf16.bf16.f32 "
        "{%0,%1,%2,%3}, {%4,%5,%6,%7}, {%8,%9}, {%0,%1,%2,%3};"
        : "+f"(d[0]), "+f"(d[1]), "+f"(d[2]), "+f"(d[3])
        : "r"(a[0]), "r"(a[1]), "r"(a[2]), "r"(a[3]), "r"(b0), "r"(b1));
}

// ============================================================
// Kernel A0: split input-projection weights into bf16 hi/lo, [n][k] layout
// ============================================================
__global__ void __launch_bounds__(256) split_w(const float* __restrict__ WK)
{
    int idx = blockIdx.x * 256 + threadIdx.x;   // over Iv*Hv
    if (idx >= Iv * Hv) return;
    int k = idx >> 10;          // / Hv
    int n = idx & 1023;         // % Hv
    float w = WK[idx];
    __nv_bfloat16 wh = __float2bfloat16(w);
    __nv_bfloat16 wl = __float2bfloat16(w - __bfloat162float(wh));
    g_wh[(size_t)n * Iv + k] = wh;
    g_wl[(size_t)n * Iv + k] = wl;
}

// ============================================================
// Kernel A: xp[t][b][h] = x[b][t][:] @ kernel[:, h] + bias[h]
// mma.sync bf16 3-term split, 128x128 tile, 8 K-chunks of 64.
// SMEM (64KB): Ahh[128][64] | Ahl | Bwh[128n][64k] | Bwl  (swizzled)
// ============================================================
__global__ void __launch_bounds__(256) xp_gemm(
    const float* __restrict__ X, const float* __restrict__ bias)
{
    extern __shared__ __align__(1024) char smem[];
    char* sAhh = smem;
    char* sAhl = smem + 16384;
    char* sBwh = smem + 32768;
    char* sBwl = smem + 49152;
    const uint32_t pAhh = smem_u32(smem);
    const uint32_t pAhl = pAhh + 16384;
    const uint32_t pBwh = pAhh + 32768;
    const uint32_t pBwl = pAhh + 49152;

    const int tid = threadIdx.x;
    const int wid = tid >> 5;
    const int lid = tid & 31;
    const int n0 = blockIdx.x * 128;
    const int m0 = blockIdx.y * 128;

    // warp tile: 2(M) x 4(N) warps; warp tile 64x32
    const int wm = wid & 1;
    const int wn = wid >> 1;

    // ldmatrix lane invariants (same as scan kernel, validated R7)
    const int rowA = ((lid >> 3) & 1) * 8 + (lid & 7);
    const int khA  = (lid >> 4) * 16;
    const int rowB = ((lid >> 4) & 1) * 8 + (lid & 7);
    const int khB  = ((lid >> 3) & 1) * 16;
    const int sw   = (lid & 7) << 4;
    const uint32_t aHiBase = pAhh + (wm * 64 + rowA) * 128;
    const uint32_t aLoBase = pAhl + (wm * 64 + rowA) * 128;
    const uint32_t bHiBase = pBwh + (wn * 32 + rowB) * 128;
    const uint32_t bLoBase = pBwl + (wn * 32 + rowB) * 128;

    const int srow = tid >> 1;          // staging row 0..127
    const int shalf = tid & 1;          // half of the row
    const uint32_t rb = srow * 128;
    const uint32_t sws = (srow & 7) << 4;
    const uint32_t soff = shalf * 64;

    float D[4][4][4];
#pragma unroll
    for (int i = 0; i < 4; i++)
#pragma unroll
        for (int j = 0; j < 4; j++)
#pragma unroll
            for (int q = 0; q < 4; q++) D[i][j][q] = 0.f;

    const float* Arow = X + (size_t)(m0 + srow) * Iv + shalf * 32;
    const __nv_bfloat16* Bh_row = g_wh + (size_t)(n0 + srow) * Iv + shalf * 32;
    const __nv_bfloat16* Bl_row = g_wl + (size_t)(n0 + srow) * Iv + shalf * 32;

#pragma unroll 1
    for (int k0 = 0; k0 < Iv; k0 += 64) {
        // ---- stage A: 32 fp32 -> 32 bf16 hi + 32 bf16 lo, swizzled ----
        {
            float f[32];
#pragma unroll
            for (int j = 0; j < 8; j++)
                *(float4*)&f[j * 4] = *(const float4*)(Arow + k0 + j * 4);
            uint32_t hi[16], lo[16];
#pragma unroll
            for (int j = 0; j < 16; j++) {
                __nv_bfloat16 h0 = __float2bfloat16(f[2 * j]);
                __nv_bfloat16 h1 = __float2bfloat16(f[2 * j + 1]);
                __nv_bfloat16 l0 = __float2bfloat16(f[2 * j] - __bfloat162float(h0));
                __nv_bfloat16 l1 = __float2bfloat16(f[2 * j + 1] - __bfloat162float(h1));
                hi[j] = (uint32_t)__bfloat16_as_ushort(h0) |
                        ((uint32_t)__bfloat16_as_ushort(h1) << 16);
                lo[j] = (uint32_t)__bfloat16_as_ushort(l0) |
                        ((uint32_t)__bfloat16_as_ushort(l1) << 16);
            }
#pragma unroll
            for (int j = 0; j < 4; j++) {
                *(uint4*)(sAhh + rb + ((soff + j * 16) ^ sws)) = *(const uint4*)&hi[j * 4];
                *(uint4*)(sAhl + rb + ((soff + j * 16) ^ sws)) = *(const uint4*)&lo[j * 4];
            }
        }
        // ---- stage B: bf16 copy from pre-split [n][k], swizzled ----
        {
            uint4 b0 = *(const uint4*)(Bh_row + k0 + 0);
            uint4 b1 = *(const uint4*)(Bh_row + k0 + 8);
            uint4 b2 = *(const uint4*)(Bh_row + k0 + 16);
            uint4 b3 = *(const uint4*)(Bh_row + k0 + 24);
            uint4 c0 = *(const uint4*)(Bl_row + k0 + 0);
            uint4 c1 = *(const uint4*)(Bl_row + k0 + 8);
            uint4 c2 = *(const uint4*)(Bl_row + k0 + 16);
            uint4 c3 = *(const uint4*)(Bl_row + k0 + 24);
            *(uint4*)(sBwh + rb + ((soff +  0) ^ sws)) = b0;
            *(uint4*)(sBwh + rb + ((soff + 16) ^ sws)) = b1;
            *(uint4*)(sBwh + rb + ((soff + 32) ^ sws)) = b2;
            *(uint4*)(sBwh + rb + ((soff + 48) ^ sws)) = b3;
            *(uint4*)(sBwl + rb + ((soff +  0) ^ sws)) = c0;
            *(uint4*)(sBwl + rb + ((soff + 16) ^ sws)) = c1;
            *(uint4*)(sBwl + rb + ((soff + 32) ^ sws)) = c2;
            *(uint4*)(sBwl + rb + ((soff + 48) ^ sws)) = c3;
        }
        __syncthreads();

        // ---- 3-term mma over this K=64 chunk ----
#pragma unroll
        for (int ks = 0; ks < 4; ks++) {
            const uint32_t koffA = ((ks * 32) | khA) ^ sw;
            const uint32_t koffB = ((ks * 32) | khB) ^ sw;
            uint32_t Ah[4][4], Al[4][4], Bh[2][4], Bl[2][4];
#pragma unroll
            for (int mt = 0; mt < 4; mt++) {
                ldsm4(Ah[mt], aHiBase + mt * 2048 + koffA);
                ldsm4(Al[mt], aLoBase + mt * 2048 + koffA);
            }
#pragma unroll
            for (int np = 0; np < 2; np++) {
                ldsm4(Bh[np], bHiBase + np * 2048 + koffB);
                ldsm4(Bl[np], bLoBase + np * 2048 + koffB);
            }
#pragma unroll
            for (int mt = 0; mt < 4; mt++) {
#pragma unroll
                for (int ntl = 0; ntl < 4; ntl++) {
                    const int np = ntl >> 1, q = (ntl & 1) * 2;
                    mma_bf16(D[mt][ntl], Ah[mt], Bh[np][q], Bh[np][q + 1]);
                    mma_bf16(D[mt][ntl], Al[mt], Bh[np][q], Bh[np][q + 1]);
                    mma_bf16(D[mt][ntl], Ah[mt], Bl[np][q], Bl[np][q + 1]);
                }
            }
        }
        __syncthreads();
    }

    // ---- epilogue: add bias, scatter to g_xp[t][b][h] ----
    {
        const int g = lid >> 2, c2 = (lid & 3) * 2;
#pragma unroll
        for (int mt = 0; mt < 4; mt++) {
#pragma unroll
            for (int ntl = 0; ntl < 4; ntl++) {
                int col = n0 + wn * 32 + ntl * 8 + c2;
                float2 bb = *(const float2*)&bias[col];
                int m0r = m0 + wm * 64 + mt * 16 + g;
#pragma unroll
                for (int half = 0; half < 2; half++) {
                    int m = m0r + half * 8;
                    int b = m >> 10;
                    int tt = m & 1023;
                    float2 v;
                    v.x = D[mt][ntl][half * 2 + 0] + bb.x;
                    v.y = D[mt][ntl][half * 2 + 1] + bb.y;
                    *(float2*)&g_xp[((size_t)tt * Bv + b) * Hv + col] = v;
                }
            }
        }
    }
}

// ============================================================
// Kernel B: persistent scan, mma.sync bf16 3-term split GEMM. (R7, proven)
// ============================================================
__global__ void __launch_bounds__(256, 1) scan_kernel(const float* __restrict__ WR)
{
    extern __shared__ __align__(1024) char smem[];
    char* sAhh = smem;
    char* sAhl = smem + 16384;
    char* sBwh = smem + 32768;
    char* sBwl = smem + 49152;
    const uint32_t pAhh = smem_u32(smem);
    const uint32_t pAhl = pAhh + 16384;
    const uint32_t pBwh = pAhh + 32768;
    const uint32_t pBwl = pAhh + 49152;

    const int tid = threadIdx.x;
    const int wid = tid >> 5;
    const int lid = tid & 31;
    const int bi = blockIdx.x;
    const int kc = bi >> 3;
    const int nt = bi & 7;
    const int kbase = kc * 64;
    const int nbase = nt * 128;
    const int e = (bi * 256 + tid) * 4;

    const int wm = wid & 1;
    const int wn = wid >> 1;

    const int rowA = ((lid >> 3) & 1) * 8 + (lid & 7);
    const int khA  = (lid >> 4) * 16;
    const int rowB = ((lid >> 4) & 1) * 8 + (lid & 7);
    const int khB  = ((lid >> 3) & 1) * 16;
    const int sw   = (lid & 7) << 4;
    const uint32_t aHiBase = pAhh + (wm * 64 + rowA) * 128;
    const uint32_t aLoBase = pAhl + (wm * 64 + rowA) * 128;
    const uint32_t bHiBase = pBwh + (wn * 32 + rowB) * 128;
    const uint32_t bLoBase = pBwl + (wn * 32 + rowB) * 128;

    // ---- preload Wr slice, split bf16 hi/lo, layout [n][k], swizzled ----
    for (int idx = tid; idx < 128 * 64; idx += 256) {
        int n = idx & 127;
        int k = idx >> 7;
        float w = WR[(size_t)(kbase + k) * Hv + nbase + n];
        __nv_bfloat16 wh = __float2bfloat16(w);
        __nv_bfloat16 wl = __float2bfloat16(w - __bfloat162float(wh));
        uint32_t off = n * 128 + ((k * 2) ^ ((n & 7) << 4));
        *(__nv_bfloat16*)(sBwh + off) = wh;
        *(__nv_bfloat16*)(sBwl + off) = wl;
    }

    *(ull*)&g_hh[e] = 0ull;
    *(ull*)&g_hl[e] = 0ull;

    float4 xpv = *(const float4*)&g_xp[e];

    grid_bar();

    const int srow = tid >> 1;
    const int soff = (tid & 1) * 64;

#pragma unroll 1
    for (int t = 0; t < Tv; t++) {
        // ---- stage h slice (bf16 hi/lo, K-major, swizzled) ----
        {
            const char* sh = (const char*)(g_hh + (size_t)srow * Hv + kbase) + soff;
            const char* sl = (const char*)(g_hl + (size_t)srow * Hv + kbase) + soff;
            uint4 h0 = __ldcg((const uint4*)sh + 0);
            uint4 h1 = __ldcg((const uint4*)sh + 1);
            uint4 h2 = __ldcg((const uint4*)sh + 2);
            uint4 h3 = __ldcg((const uint4*)sh + 3);
            uint4 l0 = __ldcg((const uint4*)sl + 0);
            uint4 l1 = __ldcg((const uint4*)sl + 1);
            uint4 l2 = __ldcg((const uint4*)sl + 2);
            uint4 l3 = __ldcg((const uint4*)sl + 3);
            uint32_t rb = srow * 128;
            uint32_t sws = (srow & 7) << 4;
            *(uint4*)(sAhh + rb + ((soff +  0) ^ sws)) = h0;
            *(uint4*)(sAhh + rb + ((soff + 16) ^ sws)) = h1;
            *(uint4*)(sAhh + rb + ((soff + 32) ^ sws)) = h2;
            *(uint4*)(sAhh + rb + ((soff + 48) ^ sws)) = h3;
            *(uint4*)(sAhl + rb + ((soff +  0) ^ sws)) = l0;
            *(uint4*)(sAhl + rb + ((soff + 16) ^ sws)) = l1;
            *(uint4*)(sAhl + rb + ((soff + 32) ^ sws)) = l2;
            *(uint4*)(sAhl + rb + ((soff + 48) ^ sws)) = l3;
        }
        __syncthreads();

        // ---- mma.sync GEMM: 128x128x64, 3 chains ----
        float D[4][4][4];
#pragma unroll
        for (int i = 0; i < 4; i++)
#pragma unroll
            for (int j = 0; j < 4; j++)
#pragma unroll
                for (int q = 0; q < 4; q++) D[i][j][q] = 0.f;

#pragma unroll
        for (int ks = 0; ks < 4; ks++) {
            const uint32_t koffA = ((ks * 32) | khA) ^ sw;
            const uint32_t koffB = ((ks * 32) | khB) ^ sw;
            uint32_t Ah[4][4], Al[4][4], Bh[2][4], Bl[2][4];
#pragma unroll
            for (int mt = 0; mt < 4; mt++) {
                ldsm4(Ah[mt], aHiBase + mt * 2048 + koffA);
                ldsm4(Al[mt], aLoBase + mt * 2048 + koffA);
            }
#pragma unroll
            for (int np = 0; np < 2; np++) {
                ldsm4(Bh[np], bHiBase + np * 2048 + koffB);
                ldsm4(Bl[np], bLoBase + np * 2048 + koffB);
            }
#pragma unroll
            for (int mt = 0; mt < 4; mt++) {
#pragma unroll
                for (int ntl = 0; ntl < 4; ntl++) {
                    const int np = ntl >> 1, q = (ntl & 1) * 2;
                    mma_bf16(D[mt][ntl], Ah[mt], Bh[np][q], Bh[np][q + 1]);
                    mma_bf16(D[mt][ntl], Al[mt], Bh[np][q], Bh[np][q + 1]);
                    mma_bf16(D[mt][ntl], Ah[mt], Bl[np][q], Bl[np][q + 1]);
                }
            }
        }

        // ---- write split-K partials ----
        {
            const int g = lid >> 2, c2 = (lid & 3) * 2;
            float* P = g_part[kc];
#pragma unroll
            for (int mt = 0; mt < 4; mt++) {
#pragma unroll
                for (int ntl = 0; ntl < 4; ntl++) {
                    int row0 = wm * 64 + mt * 16 + g;
                    int col = nbase + wn * 32 + ntl * 8 + c2;
                    float2 v0 = {D[mt][ntl][0], D[mt][ntl][1]};
                    float2 v1 = {D[mt][ntl][2], D[mt][ntl][3]};
                    *(float2*)&P[(size_t)row0 * Hv + col] = v0;
                    *(float2*)&P[(size_t)(row0 + 8) * Hv + col] = v1;
                }
            }
        }

        grid_bar();

        // ---- phase 2: reduce partials + xp + tanh -> h (bf16 hi/lo) ----
        {
            float4 s = xpv;
#pragma unroll
            for (int c = 0; c < KCHUNKS; c++) {
                float4 p = __ldcg((const float4*)&g_part[c][e]);
                s.x += p.x; s.y += p.y; s.z += p.z; s.w += p.w;
            }
            float h[4] = {tanhf(s.x), tanhf(s.y), tanhf(s.z), tanhf(s.w)};
            unsigned short hh[4], hl[4];
#pragma unroll
            for (int j = 0; j < 4; j++) {
                __nv_bfloat16 a = __float2bfloat16(h[j]);
                __nv_bfloat16 b = __float2bfloat16(h[j] - __bfloat162float(a));
                hh[j] = __bfloat16_as_ushort(a);
                hl[j] = __bfloat16_as_ushort(b);
            }
            *(ull*)&g_hh[e] = *(const ull*)hh;
            *(ull*)&g_hl[e] = *(const ull*)hl;
        }

        {
            int tn = (t + 1 < Tv) ? (t + 1) : 0;
            xpv = *(const float4*)&g_xp[(size_t)tn * (Bv * Hv) + e];
        }

        grid_bar();
    }
}

// ============================================================
// Kernel C: out[b][o] = h_last[b][:] @ fc_w[:, o] + fc_b[o]
// ============================================================
__global__ void __launch_bounds__(256, 1) fc_kernel(
    const float* __restrict__ fcw, const float* __restrict__ fcb,
    float* __restrict__ out)
{
    __shared__ float hs[Hv];
    const int b = blockIdx.x;
    for (int i = threadIdx.x; i < Hv; i += 256) {
        hs[i] = __bfloat162float(g_hh[(size_t)b * Hv + i]) +
                __bfloat162float(g_hl[(size_t)b * Hv + i]);
    }
    __syncthreads();

    const int o = threadIdx.x;
    float acc = 0.f;
#pragma unroll 4
    for (int k = 0; k < Hv; k++) {
        acc = fmaf(hs[k], fcw[(size_t)k * Ov + o], acc);
    }
    out[(size_t)b * Ov + o] = acc + fcb[o];
}

// ============================================================
extern "C" void kernel_launch(void* const* d_in, const int* in_sizes, int n_in,
                              void* d_out, int out_size)
{
    const float* x   = (const float*)d_in[0];
    const float* wk  = (const float*)d_in[1];
    const float* wr  = (const float*)d_in[2];
    const float* bs  = (const float*)d_in[3];
    const float* fcw = (const float*)d_in[4];
    const float* fcb = (const float*)d_in[5];
    float* out = (float*)d_out;

    static int smem_set = 0;
    if (!smem_set) {
        cudaFuncSetAttribute(scan_kernel,
                             cudaFuncAttributeMaxDynamicSharedMemorySize, 65536);
        cudaFuncSetAttribute(xp_gemm,
                             cudaFuncAttributeMaxDynamicSharedMemorySize, 65536);
        smem_set = 1;
    }

    split_w<<<(Iv * Hv + 255) / 256, 256>>>(wk);
    dim3 gA(Hv / 128, (Bv * Tv) / 128);
    xp_gemm<<<gA, 256, 65536>>>(x, bs);
    scan_kernel<<<NBLK_SCAN, 256, 65536>>>(wr);
    fc_kernel<<<Bv, 256>>>(fcw, fcb, out);
}

// round 9
// speedup vs baseline: 1.7297x; 1.0092x over previous
#include <cuda_runtime.h>
#include <cuda_bf16.h>
#include <math.h>
#include <cstdint>

// Problem dims
#define Bv 128
#define Tv 1024
#define Iv 512
#define Hv 1024
#define Ov 256

#define NBLK_SCAN 128   // 16 k-chunks x 8 n-tiles
#define KCHUNKS   16

typedef unsigned long long ull;

// -------- scratch (device globals: no allocation allowed) --------
__device__ __nv_bfloat16 g_xh[(size_t)Tv * Bv * Iv]; // x split hi, [t][b][i]
__device__ __nv_bfloat16 g_xl[(size_t)Tv * Bv * Iv]; // x split lo, [t][b][i]
__device__ __nv_bfloat16 g_hh[Bv * Hv];              // hidden state, bf16 hi
__device__ __nv_bfloat16 g_hl[Bv * Hv];              // hidden state, bf16 lo
__device__ float g_part[KCHUNKS][Bv * Hv];           // split-K partials (8 MB)
__device__ unsigned g_bar_count;
__device__ volatile unsigned g_bar_gen;

// -------- mma.sync / ldmatrix helpers --------
__device__ __forceinline__ uint32_t smem_u32(const void* p) {
    uint32_t a;
    asm("{ .reg .u64 t; cvta.to.shared.u64 t, %1; cvt.u32.u64 %0, t; }"
        : "=r"(a) : "l"(p));
    return a;
}
__device__ __forceinline__ void ldsm4(uint32_t r[4], uint32_t addr) {
    asm volatile("ldmatrix.sync.aligned.m8n8.x4.shared.b16 {%0,%1,%2,%3}, [%4];"
                 : "=r"(r[0]), "=r"(r[1]), "=r"(r[2]), "=r"(r[3]) : "r"(addr));
}
__device__ __forceinline__ void mma_bf16(float d[4], const uint32_t a[4],
                                         const uint32_t b0, const uint32_t b1) {
    asm volatile(
        "mma.sync.aligned.m16n8k16.row.col.f32.bf16.bf16.f32 "
        "{%0,%1,%2,%3}, {%4,%5,%6,%7}, {%8,%9}, {%0,%1,%2,%3};"
        : "+f"(d[0]), "+f"(d[1]), "+f"(d[2]), "+f"(d[3])
        : "r"(a[0]), "r"(a[1]), "r"(a[2]), "r"(a[3]), "r"(b0), "r"(b1));
}

// ============================================================
// Kernel 0: split x into bf16 hi/lo, transpose [b][t][i] -> [t][b][i]
// ============================================================
__global__ void __launch_bounds__(256) split_x(const float* __restrict__ X)
{
    size_t idx = (size_t)blockIdx.x * 256 + threadIdx.x;  // over B*T*I
    if (idx >= (size_t)Bv * Tv * Iv) return;
    int i = (int)(idx & (Iv - 1));
    int t = (int)((idx >> 9) & (Tv - 1));
    int b = (int)(idx >> 19);
    float v = X[idx];
    __nv_bfloat16 h = __float2bfloat16(v);
    __nv_bfloat16 l = __float2bfloat16(v - __bfloat162float(h));
    size_t o = ((size_t)t * Bv + b) * Iv + i;
    g_xh[o] = h;
    g_xl[o] = l;
}

// ============================================================
// Kernel B: persistent fused scan.
// CTA (kc,nt): part[kc][:,ntile] = h @ Wr[kc64,ntile] + x[t] @ Wk[kc32,ntile]
// (3-term bf16 split on both). Phase2: tanh(bias + sum partials).
// SMEM 128KB: Ahh|Ahl (h tiles) Bwh|Bwl (Wr) Xhh|Xhl (x tiles) Kwh|Kwl (Wk)
// ============================================================
__global__ void __launch_bounds__(256, 1) scan_kernel(
    const float* __restrict__ WR, const float* __restrict__ WK,
    const float* __restrict__ bias)
{
    extern __shared__ __align__(1024) char smem[];
    char* sAhh = smem;
    char* sAhl = smem + 16384;
    char* sBwh = smem + 32768;
    char* sBwl = smem + 49152;
    char* sXhh = smem + 65536;
    char* sXhl = smem + 81920;
    char* sKwh = smem + 98304;
    char* sKwl = smem + 114688;
    const uint32_t pAhh = smem_u32(smem);
    const uint32_t pAhl = pAhh + 16384;
    const uint32_t pBwh = pAhh + 32768;
    const uint32_t pBwl = pAhh + 49152;
    const uint32_t pXhh = pAhh + 65536;
    const uint32_t pXhl = pAhh + 81920;
    const uint32_t pKwh = pAhh + 98304;
    const uint32_t pKwl = pAhh + 114688;

    const int tid = threadIdx.x;
    const int wid = tid >> 5;
    const int lid = tid & 31;
    const int bi = blockIdx.x;
    const int kc = bi >> 3;            // 0..15
    const int nt = bi & 7;             // 0..7
    const int kbase = kc * 64;         // Wr K slice
    const int xbase = kc * 32;         // Wk K slice
    const int nbase = nt * 128;
    const int e = (bi * 256 + tid) * 4;

    const int wm = wid & 1;
    const int wn = wid >> 1;

    // ldmatrix lane invariants (proven R7/R8)
    const int rowA = ((lid >> 3) & 1) * 8 + (lid & 7);
    const int khA  = (lid >> 4) * 16;
    const int rowB = ((lid >> 4) & 1) * 8 + (lid & 7);
    const int khB  = ((lid >> 3) & 1) * 16;
    const int sw   = (lid & 7) << 4;
    const uint32_t aHiBase = pAhh + (wm * 64 + rowA) * 128;
    const uint32_t aLoBase = pAhl + (wm * 64 + rowA) * 128;
    const uint32_t bHiBase = pBwh + (wn * 32 + rowB) * 128;
    const uint32_t bLoBase = pBwl + (wn * 32 + rowB) * 128;
    const uint32_t xHiBase = pXhh + (wm * 64 + rowA) * 128;
    const uint32_t xLoBase = pXhl + (wm * 64 + rowA) * 128;
    const uint32_t kHiBase = pKwh + (wn * 32 + rowB) * 128;
    const uint32_t kLoBase = pKwl + (wn * 32 + rowB) * 128;

    // ---- preload Wr slice (split hi/lo, [n][k], swizzled) ----
    for (int idx = tid; idx < 128 * 64; idx += 256) {
        int n = idx & 127;
        int k = idx >> 7;
        float w = WR[(size_t)(kbase + k) * Hv + nbase + n];
        __nv_bfloat16 wh = __float2bfloat16(w);
        __nv_bfloat16 wl = __float2bfloat16(w - __bfloat162float(wh));
        uint32_t off = n * 128 + ((k * 2) ^ ((n & 7) << 4));
        *(__nv_bfloat16*)(sBwh + off) = wh;
        *(__nv_bfloat16*)(sBwl + off) = wl;
    }
    // ---- preload Wk slice (split hi/lo, [n][k], swizzled; 64B of row used) ----
    for (int idx = tid; idx < 128 * 32; idx += 256) {
        int n = idx & 127;
        int k = idx >> 7;
        float w = WK[(size_t)(xbase + k) * Hv + nbase + n];
        __nv_bfloat16 wh = __float2bfloat16(w);
        __nv_bfloat16 wl = __float2bfloat16(w - __bfloat162float(wh));
        uint32_t off = n * 128 + ((k * 2) ^ ((n & 7) << 4));
        *(__nv_bfloat16*)(sKwh + off) = wh;
        *(__nv_bfloat16*)(sKwl + off) = wl;
    }

    // zero initial hidden state
    *(ull*)&g_hh[e] = 0ull;
    *(ull*)&g_hl[e] = 0ull;

    // bias for this thread's phase-2 columns (col = tid*4 within row)
    float4 bb = *(const float4*)&bias[tid * 4];

    const int srow = tid >> 1;
    const int soff = (tid & 1) * 64;       // h tile: 64B half of 128B row
    const int xoff = (tid & 1) * 32;       // x tile: 32B half of 64B used
    const uint32_t rb = srow * 128;
    const uint32_t sws = (srow & 7) << 4;

    // ---- stage x[0] tile ----
    {
        const char* xh = (const char*)(g_xh + (size_t)srow * Iv + xbase) + xoff;
        const char* xl = (const char*)(g_xl + (size_t)srow * Iv + xbase) + xoff;
        uint4 a0 = __ldcg((const uint4*)xh + 0);
        uint4 a1 = __ldcg((const uint4*)xh + 1);
        uint4 b0 = __ldcg((const uint4*)xl + 0);
        uint4 b1 = __ldcg((const uint4*)xl + 1);
        *(uint4*)(sXhh + rb + ((xoff +  0) ^ sws)) = a0;
        *(uint4*)(sXhh + rb + ((xoff + 16) ^ sws)) = a1;
        *(uint4*)(sXhl + rb + ((xoff +  0) ^ sws)) = b0;
        *(uint4*)(sXhl + rb + ((xoff + 16) ^ sws)) = b1;
    }

    // initial grid barrier
    __threadfence();
    __syncthreads();
    if (tid == 0) {
        unsigned gen = g_bar_gen;
        unsigned prev = atomicAdd(&g_bar_count, 1u);
        if (prev == NBLK_SCAN - 1) { g_bar_count = 0; __threadfence(); g_bar_gen = gen + 1; }
        else { while (g_bar_gen == gen) { __nanosleep(64); } }
    }
    __syncthreads();

#pragma unroll 1
    for (int t = 0; t < Tv; t++) {
        // ---- stage h slice (bf16 hi/lo, K-major, swizzled) ----
        {
            const char* sh = (const char*)(g_hh + (size_t)srow * Hv + kbase) + soff;
            const char* sl = (const char*)(g_hl + (size_t)srow * Hv + kbase) + soff;
            uint4 h0 = __ldcg((const uint4*)sh + 0);
            uint4 h1 = __ldcg((const uint4*)sh + 1);
            uint4 h2 = __ldcg((const uint4*)sh + 2);
            uint4 h3 = __ldcg((const uint4*)sh + 3);
            uint4 l0 = __ldcg((const uint4*)sl + 0);
            uint4 l1 = __ldcg((const uint4*)sl + 1);
            uint4 l2 = __ldcg((const uint4*)sl + 2);
            uint4 l3 = __ldcg((const uint4*)sl + 3);
            *(uint4*)(sAhh + rb + ((soff +  0) ^ sws)) = h0;
            *(uint4*)(sAhh + rb + ((soff + 16) ^ sws)) = h1;
            *(uint4*)(sAhh + rb + ((soff + 32) ^ sws)) = h2;
            *(uint4*)(sAhh + rb + ((soff + 48) ^ sws)) = h3;
            *(uint4*)(sAhl + rb + ((soff +  0) ^ sws)) = l0;
            *(uint4*)(sAhl + rb + ((soff + 16) ^ sws)) = l1;
            *(uint4*)(sAhl + rb + ((soff + 32) ^ sws)) = l2;
            *(uint4*)(sAhl + rb + ((soff + 48) ^ sws)) = l3;
        }
        __syncthreads();

        // ---- GEMM: rec (K=64) + xp (K=32), 3-term each ----
        float D[4][4][4];
#pragma unroll
        for (int i = 0; i < 4; i++)
#pragma unroll
            for (int j = 0; j < 4; j++)
#pragma unroll
                for (int q = 0; q < 4; q++) D[i][j][q] = 0.f;

#pragma unroll
        for (int ks = 0; ks < 4; ks++) {
            const uint32_t koffA = ((ks * 32) | khA) ^ sw;
            const uint32_t koffB = ((ks * 32) | khB) ^ sw;
            uint32_t Ah[4][4], Al[4][4], Bh[2][4], Bl[2][4];
#pragma unroll
            for (int mt = 0; mt < 4; mt++) {
                ldsm4(Ah[mt], aHiBase + mt * 2048 + koffA);
                ldsm4(Al[mt], aLoBase + mt * 2048 + koffA);
            }
#pragma unroll
            for (int np = 0; np < 2; np++) {
                ldsm4(Bh[np], bHiBase + np * 2048 + koffB);
                ldsm4(Bl[np], bLoBase + np * 2048 + koffB);
            }
#pragma unroll
            for (int mt = 0; mt < 4; mt++) {
#pragma unroll
                for (int ntl = 0; ntl < 4; ntl++) {
                    const int np = ntl >> 1, q = (ntl & 1) * 2;
                    mma_bf16(D[mt][ntl], Ah[mt], Bh[np][q], Bh[np][q + 1]);
                    mma_bf16(D[mt][ntl], Al[mt], Bh[np][q], Bh[np][q + 1]);
                    mma_bf16(D[mt][ntl], Ah[mt], Bl[np][q], Bl[np][q + 1]);
                }
            }
        }
#pragma unroll
        for (int ks = 0; ks < 2; ks++) {
            const uint32_t koffA = ((ks * 32) | khA) ^ sw;
            const uint32_t koffB = ((ks * 32) | khB) ^ sw;
            uint32_t Ah[4][4], Al[4][4], Bh[2][4], Bl[2][4];
#pragma unroll
            for (int mt = 0; mt < 4; mt++) {
                ldsm4(Ah[mt], xHiBase + mt * 2048 + koffA);
                ldsm4(Al[mt], xLoBase + mt * 2048 + koffA);
            }
#pragma unroll
            for (int np = 0; np < 2; np++) {
                ldsm4(Bh[np], kHiBase + np * 2048 + koffB);
                ldsm4(Bl[np], kLoBase + np * 2048 + koffB);
            }
#pragma unroll
            for (int mt = 0; mt < 4; mt++) {
#pragma unroll
                for (int ntl = 0; ntl < 4; ntl++) {
                    const int np = ntl >> 1, q = (ntl & 1) * 2;
                    mma_bf16(D[mt][ntl], Ah[mt], Bh[np][q], Bh[np][q + 1]);
                    mma_bf16(D[mt][ntl], Al[mt], Bh[np][q], Bh[np][q + 1]);
                    mma_bf16(D[mt][ntl], Ah[mt], Bl[np][q], Bl[np][q + 1]);
                }
            }
        }

        // ---- write split-K partials ----
        {
            const int g = lid >> 2, c2 = (lid & 3) * 2;
            float* P = g_part[kc];
#pragma unroll
            for (int mt = 0; mt < 4; mt++) {
#pragma unroll
                for (int ntl = 0; ntl < 4; ntl++) {
                    int row0 = wm * 64 + mt * 16 + g;
                    int col = nbase + wn * 32 + ntl * 8 + c2;
                    float2 v0 = {D[mt][ntl][0], D[mt][ntl][1]};
                    float2 v1 = {D[mt][ntl][2], D[mt][ntl][3]};
                    *(float2*)&P[(size_t)row0 * Hv + col] = v0;
                    *(float2*)&P[(size_t)(row0 + 8) * Hv + col] = v1;
                }
            }
        }

        // ---- barrier 1, with x[t+1] staging in its shadow ----
        __threadfence();
        __syncthreads();          // all partial writes issued; GEMM done (X safe to overwrite)
        if (t + 1 < Tv) {
            const char* xh = (const char*)(g_xh + ((size_t)(t + 1) * Bv + srow) * Iv + xbase) + xoff;
            const char* xl = (const char*)(g_xl + ((size_t)(t + 1) * Bv + srow) * Iv + xbase) + xoff;
            uint4 a0 = __ldcg((const uint4*)xh + 0);
            uint4 a1 = __ldcg((const uint4*)xh + 1);
            uint4 b0 = __ldcg((const uint4*)xl + 0);
            uint4 b1 = __ldcg((const uint4*)xl + 1);
            *(uint4*)(sXhh + rb + ((xoff +  0) ^ sws)) = a0;
            *(uint4*)(sXhh + rb + ((xoff + 16) ^ sws)) = a1;
            *(uint4*)(sXhl + rb + ((xoff +  0) ^ sws)) = b0;
            *(uint4*)(sXhl + rb + ((xoff + 16) ^ sws)) = b1;
        }
        if (tid == 0) {
            unsigned gen = g_bar_gen;
            unsigned prev = atomicAdd(&g_bar_count, 1u);
            if (prev == NBLK_SCAN - 1) { g_bar_count = 0; __threadfence(); g_bar_gen = gen + 1; }
            else { while (g_bar_gen == gen) { __nanosleep(64); } }
        }
        __syncthreads();

        // ---- phase 2: reduce partials + bias + tanh -> h (bf16 hi/lo) ----
        {
            float4 s = bb;
#pragma unroll
            for (int c = 0; c < KCHUNKS; c++) {
                float4 p = __ldcg((const float4*)&g_part[c][e]);
                s.x += p.x; s.y += p.y; s.z += p.z; s.w += p.w;
            }
            float h[4] = {tanhf(s.x), tanhf(s.y), tanhf(s.z), tanhf(s.w)};
            unsigned short hh[4], hl[4];
#pragma unroll
            for (int j = 0; j < 4; j++) {
                __nv_bfloat16 a = __float2bfloat16(h[j]);
                __nv_bfloat16 b = __float2bfloat16(h[j] - __bfloat162float(a));
                hh[j] = __bfloat16_as_ushort(a);
                hl[j] = __bfloat16_as_ushort(b);
            }
            *(ull*)&g_hh[e] = *(const ull*)hh;
            *(ull*)&g_hl[e] = *(const ull*)hl;
        }

        // ---- barrier 2 ----
        __threadfence();
        __syncthreads();
        if (tid == 0) {
            unsigned gen = g_bar_gen;
            unsigned prev = atomicAdd(&g_bar_count, 1u);
            if (prev == NBLK_SCAN - 1) { g_bar_count = 0; __threadfence(); g_bar_gen = gen + 1; }
            else { while (g_bar_gen == gen) { __nanosleep(64); } }
        }
        __syncthreads();
    }
}

// ============================================================
// Kernel C: out[b][o] = h_last[b][:] @ fc_w[:, o] + fc_b[o]
// 4 independent accumulator chains (ILP) — was serial-latency-bound
// ============================================================
__global__ void __launch_bounds__(256, 1) fc_kernel(
    const float* __restrict__ fcw, const float* __restrict__ fcb,
    float* __restrict__ out)
{
    __shared__ float hs[Hv];
    const int b = blockIdx.x;
    for (int i = threadIdx.x; i < Hv; i += 256) {
        hs[i] = __bfloat162float(g_hh[(size_t)b * Hv + i]) +
                __bfloat162float(g_hl[(size_t)b * Hv + i]);
    }
    __syncthreads();

    const int o = threadIdx.x;
    float a0 = 0.f, a1 = 0.f, a2 = 0.f, a3 = 0.f;
#pragma unroll 4
    for (int k = 0; k < Hv; k += 4) {
        a0 = fmaf(hs[k + 0], fcw[(size_t)(k + 0) * Ov + o], a0);
        a1 = fmaf(hs[k + 1], fcw[(size_t)(k + 1) * Ov + o], a1);
        a2 = fmaf(hs[k + 2], fcw[(size_t)(k + 2) * Ov + o], a2);
        a3 = fmaf(hs[k + 3], fcw[(size_t)(k + 3) * Ov + o], a3);
    }
    out[(size_t)b * Ov + o] = (a0 + a1) + (a2 + a3) + fcb[o];
}

// ============================================================
extern "C" void kernel_launch(void* const* d_in, const int* in_sizes, int n_in,
                              void* d_out, int out_size)
{
    const float* x   = (const float*)d_in[0];
    const float* wk  = (const float*)d_in[1];
    const float* wr  = (const float*)d_in[2];
    const float* bs  = (const float*)d_in[3];
    const float* fcw = (const float*)d_in[4];
    const float* fcb = (const float*)d_in[5];
    float* out = (float*)d_out;

    static int smem_set = 0;
    if (!smem_set) {
        cudaFuncSetAttribute(scan_kernel,
                             cudaFuncAttributeMaxDynamicSharedMemorySize, 131072);
        smem_set = 1;
    }

    size_t nx = (size_t)Bv * Tv * Iv;
    split_x<<<(unsigned)((nx + 255) / 256), 256>>>(x);
    scan_kernel<<<NBLK_SCAN, 256, 131072>>>(wr, wk, bs);
    fc_kernel<<<Bv, 256>>>(fcw, fcb, out);
}

// round 10
// speedup vs baseline: 1.7532x; 1.0135x over previous
#include <cuda_runtime.h>
#include <cuda_bf16.h>
#include <math.h>
#include <cstdint>

// Problem dims
#define Bv 128
#define Tv 1024
#define Iv 512
#define Hv 1024
#define Ov 256

#define NBLK_SCAN 128   // 16 k-chunks x 8 n-tiles
#define KCHUNKS   16

typedef unsigned long long ull;

// -------- scratch (device globals: no allocation allowed) --------
__device__ __nv_bfloat16 g_xh[(size_t)Tv * Bv * Iv]; // x split hi, [t][b][i]
__device__ __nv_bfloat16 g_xl[(size_t)Tv * Bv * Iv]; // x split lo, [t][b][i]
__device__ __nv_bfloat16 g_hh[Bv * Hv];              // hidden state, bf16 hi
__device__ __nv_bfloat16 g_hl[Bv * Hv];              // hidden state, bf16 lo
__device__ float g_part[KCHUNKS][Bv * Hv];           // split-K partials (8 MB)
__device__ unsigned g_bar_count;
__device__ volatile unsigned g_bar_gen;

// -------- mma.sync / ldmatrix helpers --------
__device__ __forceinline__ uint32_t smem_u32(const void* p) {
    uint32_t a;
    asm("{ .reg .u64 t; cvta.to.shared.u64 t, %1; cvt.u32.u64 %0, t; }"
        : "=r"(a) : "l"(p));
    return a;
}
__device__ __forceinline__ void ldsm4(uint32_t r[4], uint32_t addr) {
    asm volatile("ldmatrix.sync.aligned.m8n8.x4.shared.b16 {%0,%1,%2,%3}, [%4];"
                 : "=r"(r[0]), "=r"(r[1]), "=r"(r[2]), "=r"(r[3]) : "r"(addr));
}
__device__ __forceinline__ void mma_bf16(float d[4], const uint32_t a[4],
                                         const uint32_t b0, const uint32_t b1) {
    asm volatile(
        "mma.sync.aligned.m16n8k16.row.col.f32.bf16.bf16.f32 "
        "{%0,%1,%2,%3}, {%4,%5,%6,%7}, {%8,%9}, {%0,%1,%2,%3};"
        : "+f"(d[0]), "+f"(d[1]), "+f"(d[2]), "+f"(d[3])
        : "r"(a[0]), "r"(a[1]), "r"(a[2]), "r"(a[3]), "r"(b0), "r"(b1));
}

__device__ __forceinline__ uint32_t bf16pack(float a, float b) {
    __nv_bfloat16 x = __float2bfloat16(a);
    __nv_bfloat16 y = __float2bfloat16(b);
    return (uint32_t)__bfloat16_as_ushort(x) |
           ((uint32_t)__bfloat16_as_ushort(y) << 16);
}

// ============================================================
// Kernel 0: split x into bf16 hi/lo, transpose [b][t][i] -> [t][b][i]
// 8 elements per thread: 2x float4 loads, 1x uint4 store per array
// ============================================================
__global__ void __launch_bounds__(256) split_x(const float* __restrict__ X)
{
    size_t idx8 = (size_t)blockIdx.x * 256 + threadIdx.x;  // over B*T*I/8
    if (idx8 >= (size_t)Bv * Tv * Iv / 8) return;
    int i = (int)(idx8 & 63) * 8;          // Iv/8 = 64 groups per row
    int t = (int)((idx8 >> 6) & 1023);
    int b = (int)(idx8 >> 16);

    const float* src = X + (((size_t)b * Tv + t) * Iv + i);
    float4 f0 = *(const float4*)(src + 0);
    float4 f1 = *(const float4*)(src + 4);
    float f[8] = {f0.x, f0.y, f0.z, f0.w, f1.x, f1.y, f1.z, f1.w};

    uint32_t hi[4], lo[4];
#pragma unroll
    for (int j = 0; j < 4; j++) {
        __nv_bfloat16 h0 = __float2bfloat16(f[2 * j]);
        __nv_bfloat16 h1 = __float2bfloat16(f[2 * j + 1]);
        hi[j] = (uint32_t)__bfloat16_as_ushort(h0) |
                ((uint32_t)__bfloat16_as_ushort(h1) << 16);
        lo[j] = bf16pack(f[2 * j] - __bfloat162float(h0),
                         f[2 * j + 1] - __bfloat162float(h1));
    }
    size_t o = (((size_t)t * Bv + b) * Iv + i);
    *(uint4*)&g_xh[o] = *(const uint4*)hi;
    *(uint4*)&g_xl[o] = *(const uint4*)lo;
}

// ============================================================
// Kernel B: persistent fused scan (R9-proven structure).
// CTA (kc,nt): part[kc][:,ntile] = h @ Wr[kc64,ntile] + x[t] @ Wk[kc32,ntile]
// (3-term bf16 split on both). Phase2: tanh(bias + sum partials).
// ============================================================
__global__ void __launch_bounds__(256, 1) scan_kernel(
    const float* __restrict__ WR, const float* __restrict__ WK,
    const float* __restrict__ bias)
{
    extern __shared__ __align__(1024) char smem[];
    char* sAhh = smem;
    char* sAhl = smem + 16384;
    char* sBwh = smem + 32768;
    char* sBwl = smem + 49152;
    char* sXhh = smem + 65536;
    char* sXhl = smem + 81920;
    char* sKwh = smem + 98304;
    char* sKwl = smem + 114688;
    const uint32_t pAhh = smem_u32(smem);
    const uint32_t pAhl = pAhh + 16384;
    const uint32_t pBwh = pAhh + 32768;
    const uint32_t pBwl = pAhh + 49152;
    const uint32_t pXhh = pAhh + 65536;
    const uint32_t pXhl = pAhh + 81920;
    const uint32_t pKwh = pAhh + 98304;
    const uint32_t pKwl = pAhh + 114688;

    const int tid = threadIdx.x;
    const int wid = tid >> 5;
    const int lid = tid & 31;
    const int bi = blockIdx.x;
    const int kc = bi >> 3;
    const int nt = bi & 7;
    const int kbase = kc * 64;
    const int xbase = kc * 32;
    const int nbase = nt * 128;
    const int e = (bi * 256 + tid) * 4;

    const int wm = wid & 1;
    const int wn = wid >> 1;

    const int rowA = ((lid >> 3) & 1) * 8 + (lid & 7);
    const int khA  = (lid >> 4) * 16;
    const int rowB = ((lid >> 4) & 1) * 8 + (lid & 7);
    const int khB  = ((lid >> 3) & 1) * 16;
    const int sw   = (lid & 7) << 4;
    const uint32_t aHiBase = pAhh + (wm * 64 + rowA) * 128;
    const uint32_t aLoBase = pAhl + (wm * 64 + rowA) * 128;
    const uint32_t bHiBase = pBwh + (wn * 32 + rowB) * 128;
    const uint32_t bLoBase = pBwl + (wn * 32 + rowB) * 128;
    const uint32_t xHiBase = pXhh + (wm * 64 + rowA) * 128;
    const uint32_t xLoBase = pXhl + (wm * 64 + rowA) * 128;
    const uint32_t kHiBase = pKwh + (wn * 32 + rowB) * 128;
    const uint32_t kLoBase = pKwl + (wn * 32 + rowB) * 128;

    // ---- preload Wr slice (split hi/lo, [n][k], swizzled) ----
    for (int idx = tid; idx < 128 * 64; idx += 256) {
        int n = idx & 127;
        int k = idx >> 7;
        float w = WR[(size_t)(kbase + k) * Hv + nbase + n];
        __nv_bfloat16 wh = __float2bfloat16(w);
        __nv_bfloat16 wl = __float2bfloat16(w - __bfloat162float(wh));
        uint32_t off = n * 128 + ((k * 2) ^ ((n & 7) << 4));
        *(__nv_bfloat16*)(sBwh + off) = wh;
        *(__nv_bfloat16*)(sBwl + off) = wl;
    }
    // ---- preload Wk slice ----
    for (int idx = tid; idx < 128 * 32; idx += 256) {
        int n = idx & 127;
        int k = idx >> 7;
        float w = WK[(size_t)(xbase + k) * Hv + nbase + n];
        __nv_bfloat16 wh = __float2bfloat16(w);
        __nv_bfloat16 wl = __float2bfloat16(w - __bfloat162float(wh));
        uint32_t off = n * 128 + ((k * 2) ^ ((n & 7) << 4));
        *(__nv_bfloat16*)(sKwh + off) = wh;
        *(__nv_bfloat16*)(sKwl + off) = wl;
    }

    *(ull*)&g_hh[e] = 0ull;
    *(ull*)&g_hl[e] = 0ull;

    float4 bb = *(const float4*)&bias[tid * 4];

    const int srow = tid >> 1;
    const int soff = (tid & 1) * 64;
    const int xoff = (tid & 1) * 32;
    const uint32_t rb = srow * 128;
    const uint32_t sws = (srow & 7) << 4;

    // ---- stage x[0] tile ----
    {
        const char* xh = (const char*)(g_xh + (size_t)srow * Iv + xbase) + xoff;
        const char* xl = (const char*)(g_xl + (size_t)srow * Iv + xbase) + xoff;
        uint4 a0 = __ldcg((const uint4*)xh + 0);
        uint4 a1 = __ldcg((const uint4*)xh + 1);
        uint4 b0 = __ldcg((const uint4*)xl + 0);
        uint4 b1 = __ldcg((const uint4*)xl + 1);
        *(uint4*)(sXhh + rb + ((xoff +  0) ^ sws)) = a0;
        *(uint4*)(sXhh + rb + ((xoff + 16) ^ sws)) = a1;
        *(uint4*)(sXhl + rb + ((xoff +  0) ^ sws)) = b0;
        *(uint4*)(sXhl + rb + ((xoff + 16) ^ sws)) = b1;
    }

    // initial grid barrier
    __threadfence();
    __syncthreads();
    if (tid == 0) {
        unsigned gen = g_bar_gen;
        unsigned prev = atomicAdd(&g_bar_count, 1u);
        if (prev == NBLK_SCAN - 1) { g_bar_count = 0; __threadfence(); g_bar_gen = gen + 1; }
        else { while (g_bar_gen == gen) {} }
    }
    __syncthreads();

#pragma unroll 1
    for (int t = 0; t < Tv; t++) {
        // ---- stage h slice (bf16 hi/lo, K-major, swizzled) ----
        {
            const char* sh = (const char*)(g_hh + (size_t)srow * Hv + kbase) + soff;
            const char* sl = (const char*)(g_hl + (size_t)srow * Hv + kbase) + soff;
            uint4 h0 = __ldcg((const uint4*)sh + 0);
            uint4 h1 = __ldcg((const uint4*)sh + 1);
            uint4 h2 = __ldcg((const uint4*)sh + 2);
            uint4 h3 = __ldcg((const uint4*)sh + 3);
            uint4 l0 = __ldcg((const uint4*)sl + 0);
            uint4 l1 = __ldcg((const uint4*)sl + 1);
            uint4 l2 = __ldcg((const uint4*)sl + 2);
            uint4 l3 = __ldcg((const uint4*)sl + 3);
            *(uint4*)(sAhh + rb + ((soff +  0) ^ sws)) = h0;
            *(uint4*)(sAhh + rb + ((soff + 16) ^ sws)) = h1;
            *(uint4*)(sAhh + rb + ((soff + 32) ^ sws)) = h2;
            *(uint4*)(sAhh + rb + ((soff + 48) ^ sws)) = h3;
            *(uint4*)(sAhl + rb + ((soff +  0) ^ sws)) = l0;
            *(uint4*)(sAhl + rb + ((soff + 16) ^ sws)) = l1;
            *(uint4*)(sAhl + rb + ((soff + 32) ^ sws)) = l2;
            *(uint4*)(sAhl + rb + ((soff + 48) ^ sws)) = l3;
        }
        __syncthreads();

        // ---- GEMM: rec (K=64) + xp (K=32), 3-term each ----
        float D[4][4][4];
#pragma unroll
        for (int i = 0; i < 4; i++)
#pragma unroll
            for (int j = 0; j < 4; j++)
#pragma unroll
                for (int q = 0; q < 4; q++) D[i][j][q] = 0.f;

#pragma unroll
        for (int ks = 0; ks < 4; ks++) {
            const uint32_t koffA = ((ks * 32) | khA) ^ sw;
            const uint32_t koffB = ((ks * 32) | khB) ^ sw;
            uint32_t Ah[4][4], Al[4][4], Bh[2][4], Bl[2][4];
#pragma unroll
            for (int mt = 0; mt < 4; mt++) {
                ldsm4(Ah[mt], aHiBase + mt * 2048 + koffA);
                ldsm4(Al[mt], aLoBase + mt * 2048 + koffA);
            }
#pragma unroll
            for (int np = 0; np < 2; np++) {
                ldsm4(Bh[np], bHiBase + np * 2048 + koffB);
                ldsm4(Bl[np], bLoBase + np * 2048 + koffB);
            }
#pragma unroll
            for (int mt = 0; mt < 4; mt++) {
#pragma unroll
                for (int ntl = 0; ntl < 4; ntl++) {
                    const int np = ntl >> 1, q = (ntl & 1) * 2;
                    mma_bf16(D[mt][ntl], Ah[mt], Bh[np][q], Bh[np][q + 1]);
                    mma_bf16(D[mt][ntl], Al[mt], Bh[np][q], Bh[np][q + 1]);
                    mma_bf16(D[mt][ntl], Ah[mt], Bl[np][q], Bl[np][q + 1]);
                }
            }
        }
#pragma unroll
        for (int ks = 0; ks < 2; ks++) {
            const uint32_t koffA = ((ks * 32) | khA) ^ sw;
            const uint32_t koffB = ((ks * 32) | khB) ^ sw;
            uint32_t Ah[4][4], Al[4][4], Bh[2][4], Bl[2][4];
#pragma unroll
            for (int mt = 0; mt < 4; mt++) {
                ldsm4(Ah[mt], xHiBase + mt * 2048 + koffA);
                ldsm4(Al[mt], xLoBase + mt * 2048 + koffA);
            }
#pragma unroll
            for (int np = 0; np < 2; np++) {
                ldsm4(Bh[np], kHiBase + np * 2048 + koffB);
                ldsm4(Bl[np], kLoBase + np * 2048 + koffB);
            }
#pragma unroll
            for (int mt = 0; mt < 4; mt++) {
#pragma unroll
                for (int ntl = 0; ntl < 4; ntl++) {
                    const int np = ntl >> 1, q = (ntl & 1) * 2;
                    mma_bf16(D[mt][ntl], Ah[mt], Bh[np][q], Bh[np][q + 1]);
                    mma_bf16(D[mt][ntl], Al[mt], Bh[np][q], Bh[np][q + 1]);
                    mma_bf16(D[mt][ntl], Ah[mt], Bl[np][q], Bl[np][q + 1]);
                }
            }
        }

        // ---- write split-K partials ----
        {
            const int g = lid >> 2, c2 = (lid & 3) * 2;
            float* P = g_part[kc];
#pragma unroll
            for (int mt = 0; mt < 4; mt++) {
#pragma unroll
                for (int ntl = 0; ntl < 4; ntl++) {
                    int row0 = wm * 64 + mt * 16 + g;
                    int col = nbase + wn * 32 + ntl * 8 + c2;
                    float2 v0 = {D[mt][ntl][0], D[mt][ntl][1]};
                    float2 v1 = {D[mt][ntl][2], D[mt][ntl][3]};
                    *(float2*)&P[(size_t)row0 * Hv + col] = v0;
                    *(float2*)&P[(size_t)(row0 + 8) * Hv + col] = v1;
                }
            }
        }

        // ---- barrier 1, with x[t+1] staging in its shadow ----
        __threadfence();
        __syncthreads();
        if (t + 1 < Tv) {
            const char* xh = (const char*)(g_xh + ((size_t)(t + 1) * Bv + srow) * Iv + xbase) + xoff;
            const char* xl = (const char*)(g_xl + ((size_t)(t + 1) * Bv + srow) * Iv + xbase) + xoff;
            uint4 a0 = __ldcg((const uint4*)xh + 0);
            uint4 a1 = __ldcg((const uint4*)xh + 1);
            uint4 b0 = __ldcg((const uint4*)xl + 0);
            uint4 b1 = __ldcg((const uint4*)xl + 1);
            *(uint4*)(sXhh + rb + ((xoff +  0) ^ sws)) = a0;
            *(uint4*)(sXhh + rb + ((xoff + 16) ^ sws)) = a1;
            *(uint4*)(sXhl + rb + ((xoff +  0) ^ sws)) = b0;
            *(uint4*)(sXhl + rb + ((xoff + 16) ^ sws)) = b1;
        }
        if (tid == 0) {
            unsigned gen = g_bar_gen;
            unsigned prev = atomicAdd(&g_bar_count, 1u);
            if (prev == NBLK_SCAN - 1) { g_bar_count = 0; __threadfence(); g_bar_gen = gen + 1; }
            else { while (g_bar_gen == gen) {} }
        }
        __syncthreads();

        // ---- phase 2: reduce partials + bias + tanh -> h (bf16 hi/lo) ----
        {
            float4 s = bb;
#pragma unroll
            for (int c = 0; c < KCHUNKS; c++) {
                float4 p = __ldcg((const float4*)&g_part[c][e]);
                s.x += p.x; s.y += p.y; s.z += p.z; s.w += p.w;
            }
            float h[4] = {tanhf(s.x), tanhf(s.y), tanhf(s.z), tanhf(s.w)};
            unsigned short hh[4], hl[4];
#pragma unroll
            for (int j = 0; j < 4; j++) {
                __nv_bfloat16 a = __float2bfloat16(h[j]);
                __nv_bfloat16 b = __float2bfloat16(h[j] - __bfloat162float(a));
                hh[j] = __bfloat16_as_ushort(a);
                hl[j] = __bfloat16_as_ushort(b);
            }
            *(ull*)&g_hh[e] = *(const ull*)hh;
            *(ull*)&g_hl[e] = *(const ull*)hl;
        }

        // ---- barrier 2 ----
        __threadfence();
        __syncthreads();
        if (tid == 0) {
            unsigned gen = g_bar_gen;
            unsigned prev = atomicAdd(&g_bar_count, 1u);
            if (prev == NBLK_SCAN - 1) { g_bar_count = 0; __threadfence(); g_bar_gen = gen + 1; }
            else { while (g_bar_gen == gen) {} }
        }
        __syncthreads();
    }
}

// ============================================================
// Kernel C: out[b][o] = h_last[b][:] @ fc_w[:, o] + fc_b[o]
// ============================================================
__global__ void __launch_bounds__(256, 1) fc_kernel(
    const float* __restrict__ fcw, const float* __restrict__ fcb,
    float* __restrict__ out)
{
    __shared__ float hs[Hv];
    const int b = blockIdx.x;
    for (int i = threadIdx.x; i < Hv; i += 256) {
        hs[i] = __bfloat162float(g_hh[(size_t)b * Hv + i]) +
                __bfloat162float(g_hl[(size_t)b * Hv + i]);
    }
    __syncthreads();

    const int o = threadIdx.x;
    float a0 = 0.f, a1 = 0.f, a2 = 0.f, a3 = 0.f;
#pragma unroll 4
    for (int k = 0; k < Hv; k += 4) {
        a0 = fmaf(hs[k + 0], fcw[(size_t)(k + 0) * Ov + o], a0);
        a1 = fmaf(hs[k + 1], fcw[(size_t)(k + 1) * Ov + o], a1);
        a2 = fmaf(hs[k + 2], fcw[(size_t)(k + 2) * Ov + o], a2);
        a3 = fmaf(hs[k + 3], fcw[(size_t)(k + 3) * Ov + o], a3);
    }
    out[(size_t)b * Ov + o] = (a0 + a1) + (a2 + a3) + fcb[o];
}

// ============================================================
extern "C" void kernel_launch(void* const* d_in, const int* in_sizes, int n_in,
                              void* d_out, int out_size)
{
    const float* x   = (const float*)d_in[0];
    const float* wk  = (const float*)d_in[1];
    const float* wr  = (const float*)d_in[2];
    const float* bs  = (const float*)d_in[3];
    const float* fcw = (const float*)d_in[4];
    const float* fcb = (const float*)d_in[5];
    float* out = (float*)d_out;

    static int smem_set = 0;
    if (!smem_set) {
        cudaFuncSetAttribute(scan_kernel,
                             cudaFuncAttributeMaxDynamicSharedMemorySize, 131072);
        smem_set = 1;
    }

    size_t nx8 = (size_t)Bv * Tv * Iv / 8;
    split_x<<<(unsigned)((nx8 + 255) / 256), 256>>>(x);
    scan_kernel<<<NBLK_SCAN, 256, 131072>>>(wr, wk, bs);
    fc_kernel<<<Bv, 256>>>(fcw, fcb, out);
}